// round 1
// baseline (speedup 1.0000x reference)
#include <cuda_runtime.h>
#include <math.h>

#define BB 16
#define TT 512
#define NF 32
#define DD 512
#define KD 96

__device__ float d_U[TT * DD];     // universal sinusoidal table rows 0..511
__device__ float d_Wt[KD * DD];    // conv weight transposed to [k][d]
__device__ int   d_cnt[BB];        // per-batch count of period-1 features

// ---------------- setup: zero counts, build U table, transpose W ----------------
__global__ void setup_kernel(const float* __restrict__ conv_w) {
    int gid = blockIdx.x * blockDim.x + threadIdx.x;
    int gsz = gridDim.x * blockDim.x;
    if (gid < BB) d_cnt[gid] = 0;
    const float sc = (float)(-9.210340371976184 / 512.0);  // -ln(10000)/d_model
    for (int e = gid; e < TT * (DD / 2); e += gsz) {
        int p = e >> 8;         // row index 0..511
        int i = e & 255;        // pair index 0..255
        float dv = expf((float)(2 * i) * sc);
        float s, c;
        sincosf((float)p * dv, &s, &c);
        d_U[p * DD + 2 * i]     = s;
        d_U[p * DD + 2 * i + 1] = c;
    }
    // Wt[k][d] = conv_w[d][i][h], k = h*32 + i, conv_w is (512, 32, 3) row-major
    for (int e = gid; e < KD * DD; e += gsz) {
        int k = e >> 9;   // /512
        int d = e & 511;
        d_Wt[e] = conv_w[d * KD + (k & 31) * 3 + (k >> 5)];
    }
}

// ---------------- DFT power argmax per (b, n) ----------------
__global__ __launch_bounds__(128) void dft_kernel(const float* __restrict__ x) {
    __shared__ float xs[TT];
    __shared__ float u[2][256];
    __shared__ float bp[128];
    __shared__ int   bk[128];
    const int b = blockIdx.x >> 5;
    const int n = blockIdx.x & 31;
    const int tid = threadIdx.x;

    for (int t = tid; t < TT; t += 128) xs[t] = x[(b * TT + t) * NF + n];
    __syncthreads();
    for (int t = tid; t < 256; t += 128) {
        float a0 = xs[t], a1 = xs[t + 256];
        u[0][t] = a0 + a1;     // even bins
        u[1][t] = a0 - a1;     // odd bins
    }
    __syncthreads();

    float best = -1.0f;
    int bestk = 0;
    for (int k = tid; k <= 256; k += 128) {
        const float* y = u[k & 1];
        float S, C;
        sincospif((float)k * (1.0f / 256.0f), &S, &C);  // step angle 2*pi*k/512
        float re = 0.f, im = 0.f, c = 1.f, s = 0.f;
        for (int seg = 0; seg < 4; seg++) {
            int tstart = seg * 64;
            int ph = (k * tstart) & 511;                // exact phase resync
            sincospif((float)ph * (1.0f / 256.0f), &s, &c);
            #pragma unroll 8
            for (int t = tstart; t < tstart + 64; t++) {
                float yv = y[t];
                re = fmaf(yv, c, re);
                im = fmaf(yv, s, im);
                float cn = fmaf(c, C, -s * S);
                s = fmaf(s, C, c * S);
                c = cn;
            }
        }
        float p = fmaf(re, re, im * im);
        if (p > best) { best = p; bestk = k; }   // ascending k -> ties keep lowest
    }
    bp[tid] = best; bk[tid] = bestk;
    __syncthreads();
    for (int off = 64; off > 0; off >>= 1) {
        if (tid < off) {
            float p2 = bp[tid + off]; int k2 = bk[tid + off];
            if (p2 > bp[tid] || (p2 == bp[tid] && k2 < bk[tid])) { bp[tid] = p2; bk[tid] = k2; }
        }
        __syncthreads();
    }
    if (tid == 0 && bk[0] == 256) atomicAdd(&d_cnt[b], 1);
}

// ---------------- fused conv-GEMM + temporal + cycle epilogue ----------------
// tile: 128 rows (consecutive t, same b) x 128 d-cols; 256 threads, 8x8 micro-tile
#define KSTAGE 48
__global__ __launch_bounds__(256, 2) void embed_kernel(
    const float* __restrict__ x, const int* __restrict__ xmark,
    float* __restrict__ out)
{
    __shared__ float slab[130 * 33];                 // x rows t0-1..t0+128, pitch 33
    __shared__ __align__(16) float Ws[KSTAGE * 128]; // W k-stage, k-major

    const int tid = threadIdx.x;
    const int mt = blockIdx.x;            // 0..63
    const int nt = blockIdx.y;            // 0..3
    const int b  = mt >> 2;
    const int t0 = (mt & 3) << 7;
    const int dbase = nt << 7;

    for (int e = tid; e < 130 * 32; e += 256) {
        int r = e >> 5, i = e & 31;
        int gt = (t0 - 1 + r) & 511;      // circular within the batch
        slab[r * 33 + i] = x[((b << 9) + gt) * NF + i];
    }

    const int m0 = (tid >> 4) << 3;
    const int d0 = (tid & 15) << 3;

    float acc[8][8];
    #pragma unroll
    for (int j = 0; j < 8; j++)
        #pragma unroll
        for (int q = 0; q < 8; q++) acc[j][q] = 0.f;

    for (int kk = 0; kk < KD / KSTAGE; kk++) {
        __syncthreads();
        for (int e = tid; e < KSTAGE * 128; e += 256) {
            int k = e >> 7, d = e & 127;
            Ws[e] = d_Wt[(kk * KSTAGE + k) * DD + dbase + d];
        }
        __syncthreads();
        #pragma unroll 4
        for (int k = 0; k < KSTAGE; k++) {
            int kg = kk * KSTAGE + k;
            int h = kg >> 5, i = kg & 31;
            const float* sp = slab + (m0 + h) * 33 + i;
            float a[8];
            #pragma unroll
            for (int j = 0; j < 8; j++) a[j] = sp[j * 33];
            float4 w0 = *reinterpret_cast<const float4*>(Ws + k * 128 + d0);
            float4 w1 = *reinterpret_cast<const float4*>(Ws + k * 128 + d0 + 4);
            #pragma unroll
            for (int j = 0; j < 8; j++) {
                acc[j][0] = fmaf(a[j], w0.x, acc[j][0]);
                acc[j][1] = fmaf(a[j], w0.y, acc[j][1]);
                acc[j][2] = fmaf(a[j], w0.z, acc[j][2]);
                acc[j][3] = fmaf(a[j], w0.w, acc[j][3]);
                acc[j][4] = fmaf(a[j], w1.x, acc[j][4]);
                acc[j][5] = fmaf(a[j], w1.y, acc[j][5]);
                acc[j][6] = fmaf(a[j], w1.z, acc[j][6]);
                acc[j][7] = fmaf(a[j], w1.w, acc[j][7]);
            }
        }
    }

    // epilogue: + temporal (4 row lookups, indices 0..6) + cycle term
    const int mb = d_cnt[b];
    const float w512 = (float)(32 - mb) * 0.03125f;
    const float modd = (float)mb * 0.03125f;     // U[0,d] = 1 on odd d
    #pragma unroll
    for (int j = 0; j < 8; j++) {
        int t = t0 + m0 + j;
        int row = (b << 9) + t;
        int4 im = *reinterpret_cast<const int4*>(xmark + row * 4);
        const float* U0 = d_U + im.x * DD;
        const float* U1 = d_U + im.y * DD;
        const float* U2 = d_U + im.z * DD;
        const float* U3 = d_U + im.w * DD;
        const float* Uc = d_U + t * DD;
        int off = dbase + d0;
        #pragma unroll
        for (int g = 0; g < 2; g++) {
            int o = off + 4 * g;
            float4 v0 = *reinterpret_cast<const float4*>(U0 + o);
            float4 v1 = *reinterpret_cast<const float4*>(U1 + o);
            float4 v2 = *reinterpret_cast<const float4*>(U2 + o);
            float4 v3 = *reinterpret_cast<const float4*>(U3 + o);
            float4 vc = *reinterpret_cast<const float4*>(Uc + o);
            float4 r;
            r.x = acc[j][4 * g + 0] + v0.x + v1.x + v2.x + v3.x + w512 * vc.x;
            r.y = acc[j][4 * g + 1] + v0.y + v1.y + v2.y + v3.y + w512 * vc.y + modd;
            r.z = acc[j][4 * g + 2] + v0.z + v1.z + v2.z + v3.z + w512 * vc.z;
            r.w = acc[j][4 * g + 3] + v0.w + v1.w + v2.w + v3.w + w512 * vc.w + modd;
            *reinterpret_cast<float4*>(out + row * DD + o) = r;
        }
    }
}

extern "C" void kernel_launch(void* const* d_in, const int* in_sizes, int n_in,
                              void* d_out, int out_size) {
    const float* x      = (const float*)d_in[0];
    const int*   xmark  = (const int*)d_in[1];
    const float* conv_w = (const float*)d_in[2];
    float* out = (float*)d_out;

    setup_kernel<<<256, 256>>>(conv_w);
    dft_kernel<<<BB * NF, 128>>>(x);
    dim3 grid(64, 4);
    embed_kernel<<<grid, 256>>>(x, xmark, out);
}

// round 3
// speedup vs baseline: 1.0104x; 1.0104x over previous
#include <cuda_runtime.h>
#include <math.h>

#define BB 16
#define TT 512
#define NF 32
#define DD 512
#define KD 96

typedef unsigned long long ull;

__device__ float d_U[TT * DD];     // universal sinusoidal table rows 0..511
__device__ float d_Wt[KD * DD];    // conv weight transposed to [k][d]
__device__ int   d_cnt[BB];        // per-batch count of period-1 features

// ---------- packed f32x2 helpers (FFMA2 is PTX-only on sm_103a) ----------
__device__ __forceinline__ ull pack2(float a, float b) {
    ull r;
    asm("mov.b64 %0, {%1, %2};" : "=l"(r)
        : "r"(__float_as_uint(a)), "r"(__float_as_uint(b)));
    return r;
}
__device__ __forceinline__ float2 unpack2(ull v) {
    unsigned lo, hi;
    asm("mov.b64 {%0, %1}, %2;" : "=r"(lo), "=r"(hi) : "l"(v));
    return make_float2(__uint_as_float(lo), __uint_as_float(hi));
}
__device__ __forceinline__ ull fma2(ull a, ull b, ull c) {
    ull d;
    asm("fma.rn.f32x2 %0, %1, %2, %3;" : "=l"(d) : "l"(a), "l"(b), "l"(c));
    return d;
}

// ---------------- setup: zero counts, build U table (rotation), transpose W ----------------
__global__ void setup_kernel(const float* __restrict__ conv_w) {
    int gid = blockIdx.x * blockDim.x + threadIdx.x;   // 8192 threads
    int gsz = gridDim.x * blockDim.x;
    if (gid < BB) d_cnt[gid] = 0;
    const float sc = (float)(-9.210340371976184 / 512.0);  // -ln(10000)/d_model
    if (gid < 4096) {
        int i  = gid & 255;       // pair column
        int pb = gid >> 8;        // 32-row strip
        float dv = expf((float)(2 * i) * sc);
        float S, C;
        sincosf(dv, &S, &C);
        int p0 = pb * 32;
        float s, c;
        sincosf((float)p0 * dv, &s, &c);
        float* base = d_U + p0 * DD + 2 * i;
        #pragma unroll 8
        for (int r = 0; r < 32; r++) {
            base[0] = s; base[1] = c;
            base += DD;
            float cn = fmaf(c, C, -s * S);
            s = fmaf(s, C, c * S);
            c = cn;
        }
    }
    // Wt[k][d] = conv_w[d][i][h], k = h*32 + i, conv_w is (512, 32, 3) row-major
    for (int e = gid; e < KD * DD; e += gsz) {
        int k = e >> 9;
        int d = e & 511;
        d_Wt[e] = conv_w[d * KD + (k & 31) * 3 + (k >> 5)];
    }
}

// ---------------- DFT power argmax per (b, n): Chebyshev twiddle + f32x2 ----------------
__global__ __launch_bounds__(128) void dft_kernel(const float* __restrict__ x) {
    __shared__ float u0[256], u1[256];
    __shared__ float red[128];
    __shared__ float bp[128];
    __shared__ int   bk[128];
    const int b = blockIdx.x >> 5;
    const int n = blockIdx.x & 31;
    const int tid = threadIdx.x;

    // load + radix-2 fold; also build alternating sum for bin 256
    float alt = 0.f;
    for (int t = tid; t < 256; t += 128) {
        float a0 = x[((b << 9) + t) * NF + n];
        float a1 = x[((b << 9) + t + 256) * NF + n];
        float e = a0 + a1, o = a0 - a1;
        u0[t] = e; u1[t] = o;
        alt += (t & 1) ? -e : e;
    }
    red[tid] = alt;
    __syncthreads();
    for (int off = 64; off > 0; off >>= 1) {
        if (tid < off) red[tid] += red[tid + off];
        __syncthreads();
    }
    const float p256 = red[0] * red[0];

    // two bins per thread: k, k+128 (same parity -> same folded sequence)
    const float* y = (tid & 1) ? u1 : u0;
    const int k0 = tid, k1 = tid + 128;
    float s, c;
    sincospif((float)k0 * (1.0f / 256.0f), &s, &c);
    const ull K0 = pack2(2.f * c, 2.f * c), M0 = pack2(-2.f * c, -2.f * c);
    sincospif((float)k1 * (1.0f / 256.0f), &s, &c);
    const ull K1 = pack2(2.f * c, 2.f * c), M1 = pack2(-2.f * c, -2.f * c);

    ull acc0 = 0ull, acc1 = 0ull;
    for (int seg = 0; seg < 8; seg++) {
        int ts = seg * 32;
        int m;
        // bin k0: states at t=ts-1 (prev) and t=ts (cur), plus negated copies
        m = (k0 * (ts - 1)) & 511; sincospif((float)m * (1.0f / 256.0f), &s, &c);
        ull Pp0 = pack2(c, s), Np0 = pack2(-c, -s);
        m = (k0 * ts) & 511;       sincospif((float)m * (1.0f / 256.0f), &s, &c);
        ull Pc0 = pack2(c, s), Nc0 = pack2(-c, -s);
        // bin k1
        m = (k1 * (ts - 1)) & 511; sincospif((float)m * (1.0f / 256.0f), &s, &c);
        ull Pp1 = pack2(c, s), Np1 = pack2(-c, -s);
        m = (k1 * ts) & 511;       sincospif((float)m * (1.0f / 256.0f), &s, &c);
        ull Pc1 = pack2(c, s), Nc1 = pack2(-c, -s);
        #pragma unroll 4
        for (int t = ts; t < ts + 32; t++) {
            float yv = y[t];
            ull YY = pack2(yv, yv);
            acc0 = fma2(YY, Pc0, acc0);
            ull Pn0 = fma2(K0, Pc0, Np0);   //  P_{t+1} = 2C*P_t - P_{t-1}
            ull Nn0 = fma2(M0, Pc0, Pp0);   // -P_{t+1}
            Pp0 = Pc0; Np0 = Nc0; Pc0 = Pn0; Nc0 = Nn0;
            acc1 = fma2(YY, Pc1, acc1);
            ull Pn1 = fma2(K1, Pc1, Np1);
            ull Nn1 = fma2(M1, Pc1, Pp1);
            Pp1 = Pc1; Np1 = Nc1; Pc1 = Pn1; Nc1 = Nn1;
        }
    }

    float2 a0v = unpack2(acc0);
    float2 a1v = unpack2(acc1);
    float pw0 = fmaf(a0v.x, a0v.x, a0v.y * a0v.y);
    float pw1 = fmaf(a1v.x, a1v.x, a1v.y * a1v.y);
    float best = pw0; int bestk = k0;
    if (pw1 > best) { best = pw1; bestk = k1; }
    bp[tid] = best; bk[tid] = bestk;
    __syncthreads();
    for (int off = 64; off > 0; off >>= 1) {
        if (tid < off) {
            float p2 = bp[tid + off]; int kk = bk[tid + off];
            if (p2 > bp[tid] || (p2 == bp[tid] && kk < bk[tid])) { bp[tid] = p2; bk[tid] = kk; }
        }
        __syncthreads();
    }
    if (tid == 0) {
        int fk = (p256 > bp[0]) ? 256 : bk[0];
        if (fk == 256) atomicAdd(&d_cnt[b], 1);
    }
}

// ---------------- fused conv-GEMM (f32x2) + temporal + cycle epilogue ----------------
#define KSTAGE 48
__global__ __launch_bounds__(256, 2) void embed_kernel(
    const float* __restrict__ x, const int* __restrict__ xmark,
    float* __restrict__ out)
{
    __shared__ float slab[130 * 33];                 // x rows t0-1..t0+128, pitch 33
    __shared__ __align__(16) float Ws[KSTAGE * 128]; // W k-stage, k-major

    const int tid = threadIdx.x;
    const int mt = blockIdx.x;            // 0..63
    const int nt = blockIdx.y;            // 0..3
    const int b  = mt >> 2;
    const int t0 = (mt & 3) << 7;
    const int dbase = nt << 7;

    for (int e = tid; e < 130 * 32; e += 256) {
        int r = e >> 5, i = e & 31;
        int gt = (t0 - 1 + r) & 511;      // circular within the batch
        slab[r * 33 + i] = x[((b << 9) + gt) * NF + i];
    }

    const int m0 = (tid >> 4) << 3;
    const int d0 = (tid & 15) << 3;

    ull acc[8][4];
    #pragma unroll
    for (int j = 0; j < 8; j++)
        #pragma unroll
        for (int q = 0; q < 4; q++) acc[j][q] = 0ull;

    for (int kk = 0; kk < KD / KSTAGE; kk++) {
        __syncthreads();
        for (int e = tid; e < KSTAGE * 128; e += 256) {
            int k = e >> 7, d = e & 127;
            Ws[e] = d_Wt[(kk * KSTAGE + k) * DD + dbase + d];
        }
        __syncthreads();
        #pragma unroll 4
        for (int k = 0; k < KSTAGE; k++) {
            int kg = kk * KSTAGE + k;
            int h = kg >> 5, i = kg & 31;
            const float* sp = slab + (m0 + h) * 33 + i;
            ull A[8];
            #pragma unroll
            for (int j = 0; j < 8; j++) { float av = sp[j * 33]; A[j] = pack2(av, av); }
            const ulonglong2* wp = reinterpret_cast<const ulonglong2*>(Ws + k * 128 + d0);
            ulonglong2 w0 = wp[0], w1 = wp[1];
            #pragma unroll
            for (int j = 0; j < 8; j++) {
                acc[j][0] = fma2(A[j], w0.x, acc[j][0]);
                acc[j][1] = fma2(A[j], w0.y, acc[j][1]);
                acc[j][2] = fma2(A[j], w1.x, acc[j][2]);
                acc[j][3] = fma2(A[j], w1.y, acc[j][3]);
            }
        }
    }

    // epilogue: + temporal (4 row lookups, indices 0..6) + cycle term
    const int mb = d_cnt[b];
    const float w512 = (float)(32 - mb) * 0.03125f;
    const float modd = (float)mb * 0.03125f;     // U[0,d] = 1 on odd d
    #pragma unroll
    for (int j = 0; j < 8; j++) {
        int t = t0 + m0 + j;
        int row = (b << 9) + t;
        int4 im = *reinterpret_cast<const int4*>(xmark + row * 4);
        const float* U0 = d_U + im.x * DD;
        const float* U1 = d_U + im.y * DD;
        const float* U2 = d_U + im.z * DD;
        const float* U3 = d_U + im.w * DD;
        const float* Uc = d_U + t * DD;
        int off = dbase + d0;
        #pragma unroll
        for (int g = 0; g < 2; g++) {
            int o = off + 4 * g;
            float2 pA = unpack2(acc[j][2 * g]);
            float2 pB = unpack2(acc[j][2 * g + 1]);
            float4 v0 = *reinterpret_cast<const float4*>(U0 + o);
            float4 v1 = *reinterpret_cast<const float4*>(U1 + o);
            float4 v2 = *reinterpret_cast<const float4*>(U2 + o);
            float4 v3 = *reinterpret_cast<const float4*>(U3 + o);
            float4 vc = *reinterpret_cast<const float4*>(Uc + o);
            float4 r;
            r.x = pA.x + v0.x + v1.x + v2.x + v3.x + w512 * vc.x;
            r.y = pA.y + v0.y + v1.y + v2.y + v3.y + w512 * vc.y + modd;
            r.z = pB.x + v0.z + v1.z + v2.z + v3.z + w512 * vc.z;
            r.w = pB.y + v0.w + v1.w + v2.w + v3.w + w512 * vc.w + modd;
            *reinterpret_cast<float4*>(out + row * DD + o) = r;
        }
    }
}

extern "C" void kernel_launch(void* const* d_in, const int* in_sizes, int n_in,
                              void* d_out, int out_size) {
    const float* x      = (const float*)d_in[0];
    const int*   xmark  = (const int*)d_in[1];
    const float* conv_w = (const float*)d_in[2];
    float* out = (float*)d_out;

    setup_kernel<<<64, 128>>>(conv_w);
    dft_kernel<<<BB * NF, 128>>>(x);
    dim3 grid(64, 4);
    embed_kernel<<<grid, 256>>>(x, xmark, out);
}

// round 4
// speedup vs baseline: 1.1296x; 1.1180x over previous
#include <cuda_runtime.h>
#include <math.h>

#define BB 16
#define TT 512
#define NF 32
#define DD 512
#define KD 96

typedef unsigned long long ull;

__device__ float d_U[TT * DD];     // universal sinusoidal table rows 0..511
__device__ float d_Wt[KD * DD];    // conv weight transposed to [k][d]
__device__ __align__(16) unsigned char d_flag[BB * NF];  // per-(b,n) Nyquist flag

// ---------- packed f32x2 helpers (FFMA2 is PTX-only on sm_103a) ----------
__device__ __forceinline__ ull pack2(float a, float b) {
    ull r;
    asm("mov.b64 %0, {%1, %2};" : "=l"(r)
        : "r"(__float_as_uint(a)), "r"(__float_as_uint(b)));
    return r;
}
__device__ __forceinline__ float2 unpack2(ull v) {
    unsigned lo, hi;
    asm("mov.b64 {%0, %1}, %2;" : "=r"(lo), "=r"(hi) : "l"(v));
    return make_float2(__uint_as_float(lo), __uint_as_float(hi));
}
__device__ __forceinline__ ull fma2(ull a, ull b, ull c) {
    ull d;
    asm("fma.rn.f32x2 %0, %1, %2, %3;" : "=l"(d) : "l"(a), "l"(b), "l"(c));
    return d;
}

// ================= prep: blocks 0..511 = DFT argmax, 512..575 = table/transpose =================
__global__ __launch_bounds__(128) void prep_kernel(
    const float* __restrict__ x, const float* __restrict__ conv_w)
{
    __shared__ float u0[256], u1[256];
    __shared__ float red[128];
    __shared__ float bp[128];
    __shared__ int   bk[128];
    const int tid = threadIdx.x;

    if (blockIdx.x >= 512) {
        // ---- setup part: U table (16-row strips) + W transpose ----
        int gid = ((blockIdx.x - 512) << 7) + tid;      // 0..8191
        int i  = gid & 255;                              // pair column
        int pb = gid >> 8;                               // 16-row strip id (0..31)
        const float sc = (float)(-9.210340371976184 / 512.0);
        float dv = expf((float)(2 * i) * sc);
        float S, C;
        sincosf(dv, &S, &C);
        int p0 = pb << 4;
        float s, c;
        sincosf((float)p0 * dv, &s, &c);
        float* base = d_U + p0 * DD + 2 * i;
        #pragma unroll
        for (int r = 0; r < 16; r++) {
            base[0] = s; base[1] = c;
            base += DD;
            float cn = fmaf(c, C, -s * S);
            s = fmaf(s, C, c * S);
            c = cn;
        }
        // Wt[k][d] = conv_w[d][i][h], k = h*32 + i
        for (int e = gid; e < KD * DD; e += 8192) {
            int k = e >> 9;
            int d = e & 511;
            d_Wt[e] = conv_w[d * KD + (k & 31) * 3 + (k >> 5)];
        }
        return;
    }

    // ---- DFT power argmax for (b, n) ----
    const int b = blockIdx.x >> 5;
    const int n = blockIdx.x & 31;

    float alt = 0.f;
    for (int t = tid; t < 256; t += 128) {
        float a0 = x[((b << 9) + t) * NF + n];
        float a1 = x[((b << 9) + t + 256) * NF + n];
        float e = a0 + a1, o = a0 - a1;
        u0[t] = e; u1[t] = o;
        alt += (t & 1) ? -e : e;
    }
    red[tid] = alt;
    __syncthreads();
    for (int off = 64; off > 0; off >>= 1) {
        if (tid < off) red[tid] += red[tid + off];
        __syncthreads();
    }
    const float p256 = red[0] * red[0];

    const float* y = (tid & 1) ? u1 : u0;
    const int k0 = tid, k1 = tid + 128;
    float s, c;
    sincospif((float)k0 * (1.0f / 256.0f), &s, &c);
    const ull K0 = pack2(2.f * c, 2.f * c), M0 = pack2(-2.f * c, -2.f * c);
    sincospif((float)k1 * (1.0f / 256.0f), &s, &c);
    const ull K1 = pack2(2.f * c, 2.f * c), M1 = pack2(-2.f * c, -2.f * c);

    ull acc0 = 0ull, acc1 = 0ull;
    for (int seg = 0; seg < 8; seg++) {
        int ts = seg * 32;
        int m;
        m = (k0 * (ts - 1)) & 511; sincospif((float)m * (1.0f / 256.0f), &s, &c);
        ull Pp0 = pack2(c, s), Np0 = pack2(-c, -s);
        m = (k0 * ts) & 511;       sincospif((float)m * (1.0f / 256.0f), &s, &c);
        ull Pc0 = pack2(c, s), Nc0 = pack2(-c, -s);
        m = (k1 * (ts - 1)) & 511; sincospif((float)m * (1.0f / 256.0f), &s, &c);
        ull Pp1 = pack2(c, s), Np1 = pack2(-c, -s);
        m = (k1 * ts) & 511;       sincospif((float)m * (1.0f / 256.0f), &s, &c);
        ull Pc1 = pack2(c, s), Nc1 = pack2(-c, -s);
        #pragma unroll 4
        for (int t = ts; t < ts + 32; t++) {
            float yv = y[t];
            ull YY = pack2(yv, yv);
            acc0 = fma2(YY, Pc0, acc0);
            ull Pn0 = fma2(K0, Pc0, Np0);   //  P_{t+1} = 2C*P_t - P_{t-1}
            ull Nn0 = fma2(M0, Pc0, Pp0);   // -P_{t+1}
            Pp0 = Pc0; Np0 = Nc0; Pc0 = Pn0; Nc0 = Nn0;
            acc1 = fma2(YY, Pc1, acc1);
            ull Pn1 = fma2(K1, Pc1, Np1);
            ull Nn1 = fma2(M1, Pc1, Pp1);
            Pp1 = Pc1; Np1 = Nc1; Pc1 = Pn1; Nc1 = Nn1;
        }
    }

    float2 a0v = unpack2(acc0);
    float2 a1v = unpack2(acc1);
    float pw0 = fmaf(a0v.x, a0v.x, a0v.y * a0v.y);
    float pw1 = fmaf(a1v.x, a1v.x, a1v.y * a1v.y);
    float best = pw0; int bestk = k0;
    if (pw1 > best) { best = pw1; bestk = k1; }
    bp[tid] = best; bk[tid] = bestk;
    __syncthreads();
    for (int off = 64; off > 0; off >>= 1) {
        if (tid < off) {
            float p2 = bp[tid + off]; int kk = bk[tid + off];
            if (p2 > bp[tid] || (p2 == bp[tid] && kk < bk[tid])) { bp[tid] = p2; bk[tid] = kk; }
        }
        __syncthreads();
    }
    if (tid == 0) {
        int fk = (p256 > bp[0]) ? 256 : bk[0];
        d_flag[blockIdx.x] = (fk == 256) ? 1 : 0;
    }
}

// ---------------- fused conv-GEMM (f32x2, tap-sharing) + temporal + cycle epilogue ----------------
__global__ __launch_bounds__(256, 2) void embed_kernel(
    const float* __restrict__ x, const int* __restrict__ xmark,
    float* __restrict__ out)
{
    __shared__ float slab[130 * 33];                 // x rows t0-1..t0+128, pitch 33
    __shared__ __align__(16) float Ws[48 * 128];     // W half-stage: rows r=h*16+ii

    const int tid = threadIdx.x;
    const int mt = blockIdx.x;            // 0..63
    const int nt = blockIdx.y;            // 0..3
    const int b  = mt >> 2;
    const int t0 = (mt & 3) << 7;
    const int dbase = nt << 7;

    for (int e = tid; e < 130 * 32; e += 256) {
        int r = e >> 5, i = e & 31;
        int gt = (t0 - 1 + r) & 511;      // circular within the batch
        slab[r * 33 + i] = x[((b << 9) + gt) * NF + i];
    }

    const int m0 = (tid >> 4) << 3;
    const int d0 = (tid & 15) << 3;

    ull acc[8][4];
    #pragma unroll
    for (int j = 0; j < 8; j++)
        #pragma unroll
        for (int q = 0; q < 4; q++) acc[j][q] = 0ull;

    for (int sg = 0; sg < 2; sg++) {      // feature halves i in [sg*16, sg*16+16)
        __syncthreads();
        for (int e = tid; e < 48 * 128; e += 256) {
            int r = e >> 7, d = e & 127;                 // r = h*16 + ii
            int k = ((r >> 4) << 5) + (sg << 4) + (r & 15);
            Ws[e] = d_Wt[k * DD + dbase + d];
        }
        __syncthreads();
        #pragma unroll 2
        for (int ii = 0; ii < 16; ii++) {
            int i = (sg << 4) + ii;
            const float* sp = slab + m0 * 33 + i;
            ull PR[10];                                  // rows m0..m0+9, duplicated pairs
            #pragma unroll
            for (int r = 0; r < 10; r++) { float v = sp[r * 33]; PR[r] = pack2(v, v); }
            #pragma unroll
            for (int h = 0; h < 3; h++) {
                const ulonglong2* wp =
                    reinterpret_cast<const ulonglong2*>(Ws + (h * 16 + ii) * 128 + d0);
                ulonglong2 w0 = wp[0], w1 = wp[1];
                #pragma unroll
                for (int j = 0; j < 8; j++) {
                    ull A = PR[j + h];
                    acc[j][0] = fma2(A, w0.x, acc[j][0]);
                    acc[j][1] = fma2(A, w0.y, acc[j][1]);
                    acc[j][2] = fma2(A, w1.x, acc[j][2]);
                    acc[j][3] = fma2(A, w1.y, acc[j][3]);
                }
            }
        }
    }

    // Nyquist count for this batch from flags (8 x dp4a over 32 bytes)
    const uint4 f1 = *reinterpret_cast<const uint4*>(d_flag + (b << 5));
    const uint4 f2 = *reinterpret_cast<const uint4*>(d_flag + (b << 5) + 16);
    int mb = 0;
    mb = __dp4a((int)f1.x, 0x01010101, mb);
    mb = __dp4a((int)f1.y, 0x01010101, mb);
    mb = __dp4a((int)f1.z, 0x01010101, mb);
    mb = __dp4a((int)f1.w, 0x01010101, mb);
    mb = __dp4a((int)f2.x, 0x01010101, mb);
    mb = __dp4a((int)f2.y, 0x01010101, mb);
    mb = __dp4a((int)f2.z, 0x01010101, mb);
    mb = __dp4a((int)f2.w, 0x01010101, mb);

    const float w512 = (float)(32 - mb) * 0.03125f;
    const float modd = (float)mb * 0.03125f;     // U[0,d] = 1 on odd d
    #pragma unroll
    for (int j = 0; j < 8; j++) {
        int t = t0 + m0 + j;
        int row = (b << 9) + t;
        int4 im = *reinterpret_cast<const int4*>(xmark + row * 4);
        const float* U0 = d_U + im.x * DD;
        const float* U1 = d_U + im.y * DD;
        const float* U2 = d_U + im.z * DD;
        const float* U3 = d_U + im.w * DD;
        const float* Uc = d_U + t * DD;
        int off = dbase + d0;
        #pragma unroll
        for (int g = 0; g < 2; g++) {
            int o = off + 4 * g;
            float2 pA = unpack2(acc[j][2 * g]);
            float2 pB = unpack2(acc[j][2 * g + 1]);
            float4 v0 = *reinterpret_cast<const float4*>(U0 + o);
            float4 v1 = *reinterpret_cast<const float4*>(U1 + o);
            float4 v2 = *reinterpret_cast<const float4*>(U2 + o);
            float4 v3 = *reinterpret_cast<const float4*>(U3 + o);
            float4 vc = *reinterpret_cast<const float4*>(Uc + o);
            float4 r;
            r.x = pA.x + v0.x + v1.x + v2.x + v3.x + w512 * vc.x;
            r.y = pA.y + v0.y + v1.y + v2.y + v3.y + w512 * vc.y + modd;
            r.z = pB.x + v0.z + v1.z + v2.z + v3.z + w512 * vc.z;
            r.w = pB.y + v0.w + v1.w + v2.w + v3.w + w512 * vc.w + modd;
            *reinterpret_cast<float4*>(out + row * DD + o) = r;
        }
    }
}

extern "C" void kernel_launch(void* const* d_in, const int* in_sizes, int n_in,
                              void* d_out, int out_size) {
    const float* x      = (const float*)d_in[0];
    const int*   xmark  = (const int*)d_in[1];
    const float* conv_w = (const float*)d_in[2];
    float* out = (float*)d_out;

    prep_kernel<<<576, 128>>>(x, conv_w);
    dim3 grid(64, 4);
    embed_kernel<<<grid, 256>>>(x, xmark, out);
}